// round 15
// baseline (speedup 1.0000x reference)
#include <cuda_runtime.h>
#include <cuda_bf16.h>
#include <cstdint>

#define DIM   256
#define NPROJ 8
#define MPIV  2048
#define KDIM  2048
#define NMAX  50000
#define CANDCAP 64
#define LDSW  40       // smem row stride (bf16) -> conflict-free ldmatrix, 80B
#define STAGES 3

// Scratch (__device__ globals per allocation rules)
__device__ __nv_bfloat16 g_Ub[(size_t)NMAX * KDIM];   // bf16 nodes for phase-1 GEMM
__device__ __nv_bfloat16 g_Vb[(size_t)MPIV * KDIM];   // bf16 pivots
__device__ float         g_V [(size_t)MPIV * KDIM];   // exact fp32 pivots * 1/8 (L2-resident)
__device__ __nv_bfloat16 g_Cb[(size_t)NMAX * MPIV];   // approx attention, bf16

// ---------------------------------------------------------------------------
// Normalization (IEEE ops): one warp per (row, p).
// ---------------------------------------------------------------------------
__global__ void normalize_kernel(const float* __restrict__ X,
                                 const float* __restrict__ W,
                                 int nrows, float scale, int isPivot) {
    int n = blockIdx.x;
    if (n >= nrows) return;
    int p    = threadIdx.x >> 5;
    int lane = threadIdx.x & 31;

    const float* x = X + (size_t)n * DIM;
    const float* w = W + (size_t)p * DIM;

    float t[8];
    float s = 0.f;
#pragma unroll
    for (int j = 0; j < 8; j++) {
        int d = lane + 32 * j;
        float v = __fmul_rn(x[d], w[d]);
        t[j] = v;
        s = __fmaf_rn(v, v, s);
    }
#pragma unroll
    for (int off = 16; off; off >>= 1)
        s = __fadd_rn(s, __shfl_xor_sync(0xffffffffu, s, off));

    float nrm = fmaxf(__fsqrt_rn(s), 1e-12f);

    __nv_bfloat16* outb = (isPivot ? g_Vb : g_Ub) + (size_t)n * KDIM + p * DIM;
    float*         outf = g_V + (size_t)n * KDIM + p * DIM;
#pragma unroll
    for (int j = 0; j < 8; j++) {
        float v = __fmul_rn(__fdiv_rn(t[j], nrm), scale);  // scale: 1.0 or 2^-3 exact
        outb[lane + 32 * j] = __float2bfloat16(v);
        if (isPivot) outf[lane + 32 * j] = v;
    }
}

// ---------------------------------------------------------------------------
// Phase-1 bf16 tensor-core GEMM, 3-stage cp.async pipeline (proven; at the
// legacy-mma throughput ceiling).
// ---------------------------------------------------------------------------
__device__ __forceinline__ uint32_t smem_u32(const void* p) {
    return (uint32_t)__cvta_generic_to_shared(p);
}
__device__ __forceinline__ void cp_async16(void* dst, const void* src) {
    asm volatile("cp.async.cg.shared.global [%0], [%1], 16;\n"
                 :: "r"(smem_u32(dst)), "l"(src));
}
__device__ __forceinline__ void ldsm_x4(uint32_t* r, uint32_t addr) {
    asm volatile("ldmatrix.sync.aligned.m8n8.x4.shared.b16 {%0,%1,%2,%3}, [%4];"
                 : "=r"(r[0]), "=r"(r[1]), "=r"(r[2]), "=r"(r[3]) : "r"(addr));
}
__device__ __forceinline__ void mma_bf16(float* c, const uint32_t* a, const uint32_t* b) {
    asm volatile("mma.sync.aligned.m16n8k16.row.col.f32.bf16.bf16.f32 "
                 "{%0,%1,%2,%3}, {%4,%5,%6,%7}, {%8,%9}, {%0,%1,%2,%3};"
                 : "+f"(c[0]), "+f"(c[1]), "+f"(c[2]), "+f"(c[3])
                 : "r"(a[0]), "r"(a[1]), "r"(a[2]), "r"(a[3]), "r"(b[0]), "r"(b[1]));
}

__global__ void __launch_bounds__(256)
gemm_bf16_kernel(int nrows) {
    __shared__ __nv_bfloat16 As[STAGES][128 * LDSW];
    __shared__ __nv_bfloat16 Bs[STAGES][128 * LDSW];

    const int tid  = threadIdx.x;
    const int warp = tid >> 5, lane = tid & 31;
    const int wm = warp >> 1, wn = warp & 1;
    const int rowBase = blockIdx.y * 128;
    const int colBase = blockIdx.x * 128;
    const int NK = KDIM / 32;

    const __nv_bfloat16* A = g_Ub;
    const __nv_bfloat16* B = g_Vb;

    float acc[2][8][4];
#pragma unroll
    for (int mi = 0; mi < 2; mi++)
#pragma unroll
        for (int nj = 0; nj < 8; nj++)
#pragma unroll
            for (int q = 0; q < 4; q++) acc[mi][nj][q] = 0.f;

    auto issue = [&](int kt) {
        int s  = kt % STAGES;
        int k0 = kt * 32;
#pragma unroll
        for (int it = 0; it < 2; it++) {
            int idx = tid + it * 256;
            int r = idx >> 2, kc = idx & 3;
            int gr = rowBase + r; if (gr >= nrows) gr = nrows - 1;
            cp_async16(&As[s][r * LDSW + kc * 8], A + (size_t)gr * KDIM + k0 + kc * 8);
            cp_async16(&Bs[s][r * LDSW + kc * 8], B + (size_t)(colBase + r) * KDIM + k0 + kc * 8);
        }
        asm volatile("cp.async.commit_group;");
    };

    issue(0);
    issue(1);

    for (int kt = 0; kt < NK; kt++) {
        asm volatile("cp.async.wait_group 1;");
        __syncthreads();
        if (kt + 2 < NK) issue(kt + 2);
        else asm volatile("cp.async.commit_group;");

        const int s = kt % STAGES;
#pragma unroll
        for (int kk = 0; kk < 2; kk++) {
            const int ko = kk * 16;
            uint32_t a[2][4];
#pragma unroll
            for (int mi = 0; mi < 2; mi++) {
                int r = wm * 32 + mi * 16 + (lane & 15);
                int c = ko + (lane >> 4) * 8;
                ldsm_x4(a[mi], smem_u32(&As[s][r * LDSW + c]));
            }
            uint32_t b[8][2];
#pragma unroll
            for (int p = 0; p < 4; p++) {
                int r = wn * 64 + p * 16 + ((lane >> 4) & 1) * 8 + (lane & 7);
                int c = ko + ((lane >> 3) & 1) * 8;
                uint32_t rr[4];
                ldsm_x4(rr, smem_u32(&Bs[s][r * LDSW + c]));
                b[2 * p][0] = rr[0]; b[2 * p][1] = rr[1];
                b[2 * p + 1][0] = rr[2]; b[2 * p + 1][1] = rr[3];
            }
#pragma unroll
            for (int mi = 0; mi < 2; mi++)
#pragma unroll
                for (int nj = 0; nj < 8; nj++)
                    mma_bf16(acc[mi][nj], a[mi], b[nj]);
        }
    }

    const int g = lane >> 2, t = lane & 3;
#pragma unroll
    for (int mi = 0; mi < 2; mi++) {
        int r0 = rowBase + wm * 32 + mi * 16 + g;
#pragma unroll
        for (int nj = 0; nj < 8; nj++) {
            int col = colBase + wn * 64 + nj * 8 + 2 * t;
            if (r0 < nrows) {
                __nv_bfloat162 pv = __float22bfloat162_rn(
                    make_float2(acc[mi][nj][0], acc[mi][nj][1]));
                *(__nv_bfloat162*)(g_Cb + (size_t)r0 * MPIV + col) = pv;
            }
            if (r0 + 8 < nrows) {
                __nv_bfloat162 pv = __float22bfloat162_rn(
                    make_float2(acc[mi][nj][2], acc[mi][nj][3]));
                *(__nv_bfloat162*)(g_Cb + (size_t)(r0 + 8) * MPIV + col) = pv;
            }
        }
    }
}

// ---------------------------------------------------------------------------
// Fused select + refine.
//  - 16-bit monotone keys, 2-pass radix select of rank-(k+6)
//  - phase C: split-K=4. warp = (team of 2, quarter). u-quarter in 16 regs;
//    inner loop LDG-only. Quarters merged deterministically via TwoSum.
//  - 5 blocks/SM target (51-reg cap)
// ---------------------------------------------------------------------------
__device__ __forceinline__ unsigned m16(unsigned u) {   // bf16 raw -> monotone 16-bit
    return (u & 0x8000u) ? ((~u) & 0xFFFFu) : (u | 0x8000u);
}

// warp reduction of a (S, CP) Kahan pair via TwoSum; valid on all lanes after
__device__ __forceinline__ void kahan_warp_reduce_pair(float& S, float& CP) {
#pragma unroll
    for (int off = 16; off; off >>= 1) {
        float s2 = __shfl_xor_sync(0xffffffffu, S, off);
        float c2 = __shfl_xor_sync(0xffffffffu, CP, off);
        float t  = __fadd_rn(S, s2);
        float z  = __fsub_rn(t, S);
        float e  = __fadd_rn(__fsub_rn(S, __fsub_rn(t, z)), __fsub_rn(s2, z));
        S  = t;
        CP = __fadd_rn(__fadd_rn(CP, c2), e);
    }
}

__global__ void __launch_bounds__(256, 5)
select_refine_kernel(float* __restrict__ out,
                     const float* __restrict__ nodes,
                     const float* __restrict__ W,
                     int nrows, const int* __restrict__ topk_ptr) {
    int row = blockIdx.x;
    if (row >= nrows) return;

    __shared__ float    uex[KDIM];
    __shared__ unsigned hist[256];
    __shared__ unsigned warpsum[8];
    __shared__ float    pS [CANDCAP][4];
    __shared__ float    pCP[CANDCAP][4];
    __shared__ float    cval[CANDCAP];
    __shared__ int      cidx[CANDCAP];
    __shared__ unsigned s_b0;
    __shared__ unsigned s_T;
    __shared__ int      s_krem;
    __shared__ int      s_cnt;

    float* rowp = out + (size_t)row * MPIV;
    const int tid  = threadIdx.x;
    const int warp = tid >> 5, lane = tid & 31;

    // 8 bf16 keys per thread in ONE uint4 load
    unsigned key[8];
    {
        uint4 kv = *(const uint4*)(g_Cb + (size_t)row * MPIV + tid * 8);
        unsigned w0 = kv.x, w1 = kv.y, w2 = kv.z, w3 = kv.w;
        key[0] = m16(w0 & 0xFFFFu); key[1] = m16(w0 >> 16);
        key[2] = m16(w1 & 0xFFFFu); key[3] = m16(w1 >> 16);
        key[4] = m16(w2 & 0xFFFFu); key[5] = m16(w2 >> 16);
        key[6] = m16(w3 & 0xFFFFu); key[7] = m16(w3 >> 16);
    }

    int k = topk_ptr ? __ldg(topk_ptr) : 32;
    // zero the output row NOW -- stores drain behind all later phases
    {
        float4 z = make_float4(0.f, 0.f, 0.f, 0.f);
        for (int i = tid; i < MPIV / 4; i += 256) ((float4*)rowp)[i] = z;
    }
    if (k <= 0) return;
    if (k > CANDCAP - 6) k = CANDCAP - 6;   // dataset: k=32; guard the cap
    int R = k + 6;

    if (tid == 0) { s_krem = R; s_cnt = 0; }

    // exact u recompute (identical IEEE op order to normalize)
    {
        const float* x = nodes + (size_t)row * DIM;
        const float* w = W + (size_t)warp * DIM;
        float t[8];
        float s = 0.f;
#pragma unroll
        for (int j = 0; j < 8; j++) {
            int d = lane + 32 * j;
            float v = __fmul_rn(x[d], w[d]);
            t[j] = v;
            s = __fmaf_rn(v, v, s);
        }
#pragma unroll
        for (int off = 16; off; off >>= 1)
            s = __fadd_rn(s, __shfl_xor_sync(0xffffffffu, s, off));
        float nrm = fmaxf(__fsqrt_rn(s), 1e-12f);
#pragma unroll
        for (int j = 0; j < 8; j++)
            uex[warp * DIM + lane + 32 * j] = __fdiv_rn(t[j], nrm);
    }
    __syncthreads();

    // --- 2-pass radix select (8-bit digits) of rank-R 16-bit key ---
#pragma unroll
    for (int pass = 0; pass < 2; pass++) {
        hist[tid] = 0u;
        __syncthreads();
        int krem = s_krem;
        unsigned b0 = (pass == 0) ? 0u : s_b0;
#pragma unroll
        for (int it = 0; it < 8; it++) {
            if (pass == 0)
                atomicAdd(&hist[key[it] >> 8], 1u);
            else if ((key[it] >> 8) == b0)
                atomicAdd(&hist[key[it] & 255u], 1u);
        }
        __syncthreads();
        unsigned h = hist[255 - tid];
        unsigned x = h;
#pragma unroll
        for (int off = 1; off < 32; off <<= 1) {
            unsigned y = __shfl_up_sync(0xffffffffu, x, off);
            if (lane >= off) x += y;
        }
        if (lane == 31) warpsum[warp] = x;
        __syncthreads();
        unsigned add = 0;
#pragma unroll
        for (int w = 0; w < 8; w++)
            add += (w < warp) ? warpsum[w] : 0u;
        unsigned S = x + add;
        if ((int)S >= krem && (int)(S - h) < krem) {
            if (pass == 0) s_b0 = (unsigned)(255 - tid);
            else           s_T  = (s_b0 << 8) | (unsigned)(255 - tid);
            s_krem = krem - (int)(S - h);
        }
        __syncthreads();
    }

    unsigned T = s_T;

    // gather candidates
#pragma unroll
    for (int it = 0; it < 8; it++) {
        if (key[it] >= T) {
            int slot = atomicAdd(&s_cnt, 1);
            if (slot < CANDCAP) cidx[slot] = tid * 8 + it;
        }
    }
    __syncthreads();
    int cnt = (s_cnt < CANDCAP) ? s_cnt : CANDCAP;

    // --- phase C: split-K=4 exact dots. team = warp>>2, quarter = warp&3 ---
    {
        const int team    = warp >> 2;           // 0..1
        const int quarter = warp & 3;            // 0..3
        const int koff    = quarter * (KDIM / 4);

        // u-quarter into registers: 512 elems / 32 lanes = 4 float4 per lane
        float4 ureg[4];
        const float4* uh = (const float4*)(uex + koff);
#pragma unroll
        for (int t = 0; t < 4; t++)
            ureg[t] = uh[lane + 32 * t];

        for (int c = team; c < cnt; c += 2) {
            const float4* vh = (const float4*)(g_V + (size_t)cidx[c] * KDIM + koff);

            float s[2] = {0.f, 0.f}, cp[2] = {0.f, 0.f};
#pragma unroll
            for (int t = 0; t < 4; t++) {
                float4 a = ureg[t];
                float4 b = vh[lane + 32 * t];
                float p0 = __fmaf_rn(a.y, b.y, __fmul_rn(a.x, b.x));
                float p1 = __fmaf_rn(a.w, b.w, __fmul_rn(a.z, b.z));
                {
                    float y  = __fsub_rn(p0, cp[0]);
                    float s2 = __fadd_rn(s[0], y);
                    cp[0]    = __fsub_rn(__fsub_rn(s2, s[0]), y);
                    s[0]     = s2;
                }
                {
                    float y  = __fsub_rn(p1, cp[1]);
                    float s2 = __fadd_rn(s[1], y);
                    cp[1]    = __fsub_rn(__fsub_rn(s2, s[1]), y);
                    s[1]     = s2;
                }
            }
            // merge the 2 chains via TwoSum
            float S = s[0], CP = cp[0];
            {
                float t  = __fadd_rn(S, s[1]);
                float z  = __fsub_rn(t, S);
                float e  = __fadd_rn(__fsub_rn(S, __fsub_rn(t, z)), __fsub_rn(s[1], z));
                S  = t;
                CP = __fadd_rn(__fadd_rn(CP, cp[1]), e);
            }
            kahan_warp_reduce_pair(S, CP);
            if (lane == 0) { pS[c][quarter] = S; pCP[c][quarter] = CP; }
        }
    }
    __syncthreads();

    // merge quarters deterministically (q0 + q1 + q2 + q3) per candidate
    if (tid < cnt) {
        float S = pS[tid][0], CP = pCP[tid][0];
#pragma unroll
        for (int q = 1; q < 4; q++) {
            float Sq = pS[tid][q];
            float t  = __fadd_rn(S, Sq);
            float z  = __fsub_rn(t, S);
            float e  = __fadd_rn(__fsub_rn(S, __fsub_rn(t, z)), __fsub_rn(Sq, z));
            S  = t;
            CP = __fadd_rn(__fadd_rn(CP, pCP[tid][q]), e);
        }
        cval[tid] = __fadd_rn(S, CP);
    }
    __syncthreads();

    // exact top-k among candidates (tie: lowest index), scatter
    if (tid < cnt) {
        float my = cval[tid];
        int   mi = cidx[tid];
        int rank = 0;
        for (int j = 0; j < cnt; j++) {
            float vj = cval[j];
            if (vj > my || (vj == my && cidx[j] < mi)) rank++;
        }
        if (rank < k)
            rowp[mi] = my;
    }
}

// ---------------------------------------------------------------------------
extern "C" void kernel_launch(void* const* d_in, const int* in_sizes, int n_in,
                              void* d_out, int out_size) {
    const float* nodes  = (const float*)d_in[0];
    const float* pivots = (const float*)d_in[1];
    const float* W      = (const float*)d_in[2];
    const int*   topk   = (n_in > 3) ? (const int*)d_in[3] : nullptr;

    int N = in_sizes[0] / DIM;
    int M = in_sizes[1] / DIM;
    if (N > NMAX) N = NMAX;

    float* out = (float*)d_out;

    normalize_kernel<<<N, 256>>>(nodes,  W, N, 1.0f,   0);
    normalize_kernel<<<M, 256>>>(pivots, W, M, 0.125f, 1);

    dim3 ggrid(MPIV / 128, (N + 127) / 128);
    gemm_bf16_kernel<<<ggrid, 256>>>(N);

    select_refine_kernel<<<N, 256>>>(out, nodes, W, N, topk);

    (void)out_size;
}

// round 16
// speedup vs baseline: 1.0375x; 1.0375x over previous
#include <cuda_runtime.h>
#include <cuda_bf16.h>
#include <cstdint>

#define DIM   256
#define NPROJ 8
#define MPIV  2048
#define KDIM  2048
#define NMAX  50000
#define CANDCAP 64
#define LDSW  40       // smem row stride (bf16) -> conflict-free ldmatrix, 80B
#define STAGES 3

// Scratch (__device__ globals per allocation rules)
__device__ __nv_bfloat16 g_Ub[(size_t)NMAX * KDIM];   // bf16 nodes for phase-1 GEMM
__device__ __nv_bfloat16 g_Vb[(size_t)MPIV * KDIM];   // bf16 pivots
__device__ float         g_V [(size_t)MPIV * KDIM];   // exact fp32 pivots * 1/8 (L2-resident)
__device__ __nv_bfloat16 g_Cb[(size_t)NMAX * MPIV];   // approx attention, bf16

// ---------------------------------------------------------------------------
// Normalization (IEEE ops): one warp per (row, p).
// ---------------------------------------------------------------------------
__global__ void normalize_kernel(const float* __restrict__ X,
                                 const float* __restrict__ W,
                                 int nrows, float scale, int isPivot) {
    int n = blockIdx.x;
    if (n >= nrows) return;
    int p    = threadIdx.x >> 5;
    int lane = threadIdx.x & 31;

    const float* x = X + (size_t)n * DIM;
    const float* w = W + (size_t)p * DIM;

    float t[8];
    float s = 0.f;
#pragma unroll
    for (int j = 0; j < 8; j++) {
        int d = lane + 32 * j;
        float v = __fmul_rn(x[d], w[d]);
        t[j] = v;
        s = __fmaf_rn(v, v, s);
    }
#pragma unroll
    for (int off = 16; off; off >>= 1)
        s = __fadd_rn(s, __shfl_xor_sync(0xffffffffu, s, off));

    float nrm = fmaxf(__fsqrt_rn(s), 1e-12f);

    __nv_bfloat16* outb = (isPivot ? g_Vb : g_Ub) + (size_t)n * KDIM + p * DIM;
    float*         outf = g_V + (size_t)n * KDIM + p * DIM;
#pragma unroll
    for (int j = 0; j < 8; j++) {
        float v = __fmul_rn(__fdiv_rn(t[j], nrm), scale);  // scale: 1.0 or 2^-3 exact
        outb[lane + 32 * j] = __float2bfloat16(v);
        if (isPivot) outf[lane + 32 * j] = v;
    }
}

// ---------------------------------------------------------------------------
// Phase-1 bf16 tensor-core GEMM, 3-stage cp.async pipeline (proven; at the
// legacy-mma throughput ceiling).
// ---------------------------------------------------------------------------
__device__ __forceinline__ uint32_t smem_u32(const void* p) {
    return (uint32_t)__cvta_generic_to_shared(p);
}
__device__ __forceinline__ void cp_async16(void* dst, const void* src) {
    asm volatile("cp.async.cg.shared.global [%0], [%1], 16;\n"
                 :: "r"(smem_u32(dst)), "l"(src));
}
__device__ __forceinline__ void ldsm_x4(uint32_t* r, uint32_t addr) {
    asm volatile("ldmatrix.sync.aligned.m8n8.x4.shared.b16 {%0,%1,%2,%3}, [%4];"
                 : "=r"(r[0]), "=r"(r[1]), "=r"(r[2]), "=r"(r[3]) : "r"(addr));
}
__device__ __forceinline__ void mma_bf16(float* c, const uint32_t* a, const uint32_t* b) {
    asm volatile("mma.sync.aligned.m16n8k16.row.col.f32.bf16.bf16.f32 "
                 "{%0,%1,%2,%3}, {%4,%5,%6,%7}, {%8,%9}, {%0,%1,%2,%3};"
                 : "+f"(c[0]), "+f"(c[1]), "+f"(c[2]), "+f"(c[3])
                 : "r"(a[0]), "r"(a[1]), "r"(a[2]), "r"(a[3]), "r"(b[0]), "r"(b[1]));
}

__global__ void __launch_bounds__(256)
gemm_bf16_kernel(int nrows) {
    __shared__ __nv_bfloat16 As[STAGES][128 * LDSW];
    __shared__ __nv_bfloat16 Bs[STAGES][128 * LDSW];

    const int tid  = threadIdx.x;
    const int warp = tid >> 5, lane = tid & 31;
    const int wm = warp >> 1, wn = warp & 1;
    const int rowBase = blockIdx.y * 128;
    const int colBase = blockIdx.x * 128;
    const int NK = KDIM / 32;

    const __nv_bfloat16* A = g_Ub;
    const __nv_bfloat16* B = g_Vb;

    float acc[2][8][4];
#pragma unroll
    for (int mi = 0; mi < 2; mi++)
#pragma unroll
        for (int nj = 0; nj < 8; nj++)
#pragma unroll
            for (int q = 0; q < 4; q++) acc[mi][nj][q] = 0.f;

    auto issue = [&](int kt) {
        int s  = kt % STAGES;
        int k0 = kt * 32;
#pragma unroll
        for (int it = 0; it < 2; it++) {
            int idx = tid + it * 256;
            int r = idx >> 2, kc = idx & 3;
            int gr = rowBase + r; if (gr >= nrows) gr = nrows - 1;
            cp_async16(&As[s][r * LDSW + kc * 8], A + (size_t)gr * KDIM + k0 + kc * 8);
            cp_async16(&Bs[s][r * LDSW + kc * 8], B + (size_t)(colBase + r) * KDIM + k0 + kc * 8);
        }
        asm volatile("cp.async.commit_group;");
    };

    issue(0);
    issue(1);

    for (int kt = 0; kt < NK; kt++) {
        asm volatile("cp.async.wait_group 1;");
        __syncthreads();
        if (kt + 2 < NK) issue(kt + 2);
        else asm volatile("cp.async.commit_group;");

        const int s = kt % STAGES;
#pragma unroll
        for (int kk = 0; kk < 2; kk++) {
            const int ko = kk * 16;
            uint32_t a[2][4];
#pragma unroll
            for (int mi = 0; mi < 2; mi++) {
                int r = wm * 32 + mi * 16 + (lane & 15);
                int c = ko + (lane >> 4) * 8;
                ldsm_x4(a[mi], smem_u32(&As[s][r * LDSW + c]));
            }
            uint32_t b[8][2];
#pragma unroll
            for (int p = 0; p < 4; p++) {
                int r = wn * 64 + p * 16 + ((lane >> 4) & 1) * 8 + (lane & 7);
                int c = ko + ((lane >> 3) & 1) * 8;
                uint32_t rr[4];
                ldsm_x4(rr, smem_u32(&Bs[s][r * LDSW + c]));
                b[2 * p][0] = rr[0]; b[2 * p][1] = rr[1];
                b[2 * p + 1][0] = rr[2]; b[2 * p + 1][1] = rr[3];
            }
#pragma unroll
            for (int mi = 0; mi < 2; mi++)
#pragma unroll
                for (int nj = 0; nj < 8; nj++)
                    mma_bf16(acc[mi][nj], a[mi], b[nj]);
        }
    }

    const int g = lane >> 2, t = lane & 3;
#pragma unroll
    for (int mi = 0; mi < 2; mi++) {
        int r0 = rowBase + wm * 32 + mi * 16 + g;
#pragma unroll
        for (int nj = 0; nj < 8; nj++) {
            int col = colBase + wn * 64 + nj * 8 + 2 * t;
            if (r0 < nrows) {
                __nv_bfloat162 pv = __float22bfloat162_rn(
                    make_float2(acc[mi][nj][0], acc[mi][nj][1]));
                *(__nv_bfloat162*)(g_Cb + (size_t)r0 * MPIV + col) = pv;
            }
            if (r0 + 8 < nrows) {
                __nv_bfloat162 pv = __float22bfloat162_rn(
                    make_float2(acc[mi][nj][2], acc[mi][nj][3]));
                *(__nv_bfloat162*)(g_Cb + (size_t)(r0 + 8) * MPIV + col) = pv;
            }
        }
    }
}

// ---------------------------------------------------------------------------
// Fused select + refine (R13 proven structure).
//  - 16-bit monotone keys, 2-pass radix select of rank-(k+4)
//  - phase C: split-K=2. warp = (team of 4, half). u-half in 32 regs;
//    inner loop __ldg of v only (no LDS). Halves merged via TwoSum.
// ---------------------------------------------------------------------------
__device__ __forceinline__ unsigned m16(unsigned u) {   // bf16 raw -> monotone 16-bit
    return (u & 0x8000u) ? ((~u) & 0xFFFFu) : (u | 0x8000u);
}

// warp reduction of a (S, CP) Kahan pair via TwoSum; valid on all lanes after
__device__ __forceinline__ void kahan_warp_reduce_pair(float& S, float& CP) {
#pragma unroll
    for (int off = 16; off; off >>= 1) {
        float s2 = __shfl_xor_sync(0xffffffffu, S, off);
        float c2 = __shfl_xor_sync(0xffffffffu, CP, off);
        float t  = __fadd_rn(S, s2);
        float z  = __fsub_rn(t, S);
        float e  = __fadd_rn(__fsub_rn(S, __fsub_rn(t, z)), __fsub_rn(s2, z));
        S  = t;
        CP = __fadd_rn(__fadd_rn(CP, c2), e);
    }
}

__global__ void __launch_bounds__(256, 4)
select_refine_kernel(float* __restrict__ out,
                     const float* __restrict__ nodes,
                     const float* __restrict__ W,
                     int nrows, const int* __restrict__ topk_ptr) {
    int row = blockIdx.x;
    if (row >= nrows) return;

    __shared__ float    uex[KDIM];
    __shared__ unsigned hist[256];
    __shared__ unsigned warpsum[8];
    __shared__ float    pS [CANDCAP][2];
    __shared__ float    pCP[CANDCAP][2];
    __shared__ float    cval[CANDCAP];
    __shared__ int      cidx[CANDCAP];
    __shared__ unsigned s_b0;
    __shared__ unsigned s_T;
    __shared__ int      s_krem;
    __shared__ int      s_cnt;

    float* rowp = out + (size_t)row * MPIV;
    const int tid  = threadIdx.x;
    const int warp = tid >> 5, lane = tid & 31;

    // 8 bf16 keys per thread in ONE uint4 load (non-coherent path)
    unsigned key[8];
    {
        uint4 kv = __ldg((const uint4*)(g_Cb + (size_t)row * MPIV + tid * 8));
        unsigned w0 = kv.x, w1 = kv.y, w2 = kv.z, w3 = kv.w;
        key[0] = m16(w0 & 0xFFFFu); key[1] = m16(w0 >> 16);
        key[2] = m16(w1 & 0xFFFFu); key[3] = m16(w1 >> 16);
        key[4] = m16(w2 & 0xFFFFu); key[5] = m16(w2 >> 16);
        key[6] = m16(w3 & 0xFFFFu); key[7] = m16(w3 >> 16);
    }

    int k = topk_ptr ? __ldg(topk_ptr) : 32;
    // zero the output row NOW -- stores drain behind all later phases
    {
        float4 z = make_float4(0.f, 0.f, 0.f, 0.f);
        for (int i = tid; i < MPIV / 4; i += 256) ((float4*)rowp)[i] = z;
    }
    if (k <= 0) return;
    if (k > CANDCAP - 4) k = CANDCAP - 4;   // dataset: k=32; guard the cap
    int R = k + 4;

    if (tid == 0) { s_krem = R; s_cnt = 0; }

    // exact u recompute (identical IEEE op order to normalize)
    {
        const float* x = nodes + (size_t)row * DIM;
        const float* w = W + (size_t)warp * DIM;
        float t[8];
        float s = 0.f;
#pragma unroll
        for (int j = 0; j < 8; j++) {
            int d = lane + 32 * j;
            float v = __fmul_rn(x[d], w[d]);
            t[j] = v;
            s = __fmaf_rn(v, v, s);
        }
#pragma unroll
        for (int off = 16; off; off >>= 1)
            s = __fadd_rn(s, __shfl_xor_sync(0xffffffffu, s, off));
        float nrm = fmaxf(__fsqrt_rn(s), 1e-12f);
#pragma unroll
        for (int j = 0; j < 8; j++)
            uex[warp * DIM + lane + 32 * j] = __fdiv_rn(t[j], nrm);
    }
    __syncthreads();

    // --- 2-pass radix select (8-bit digits) of rank-R 16-bit key ---
#pragma unroll
    for (int pass = 0; pass < 2; pass++) {
        hist[tid] = 0u;
        __syncthreads();
        int krem = s_krem;
        unsigned b0 = (pass == 0) ? 0u : s_b0;
#pragma unroll
        for (int it = 0; it < 8; it++) {
            if (pass == 0)
                atomicAdd(&hist[key[it] >> 8], 1u);
            else if ((key[it] >> 8) == b0)
                atomicAdd(&hist[key[it] & 255u], 1u);
        }
        __syncthreads();
        unsigned h = hist[255 - tid];
        unsigned x = h;
#pragma unroll
        for (int off = 1; off < 32; off <<= 1) {
            unsigned y = __shfl_up_sync(0xffffffffu, x, off);
            if (lane >= off) x += y;
        }
        if (lane == 31) warpsum[warp] = x;
        __syncthreads();
        unsigned add = 0;
#pragma unroll
        for (int w = 0; w < 8; w++)
            add += (w < warp) ? warpsum[w] : 0u;
        unsigned S = x + add;
        if ((int)S >= krem && (int)(S - h) < krem) {
            if (pass == 0) s_b0 = (unsigned)(255 - tid);
            else           s_T  = (s_b0 << 8) | (unsigned)(255 - tid);
            s_krem = krem - (int)(S - h);
        }
        __syncthreads();
    }

    unsigned T = s_T;

    // gather candidates
#pragma unroll
    for (int it = 0; it < 8; it++) {
        if (key[it] >= T) {
            int slot = atomicAdd(&s_cnt, 1);
            if (slot < CANDCAP) cidx[slot] = tid * 8 + it;
        }
    }
    __syncthreads();
    int cnt = (s_cnt < CANDCAP) ? s_cnt : CANDCAP;

    // --- phase C: split-K=2 exact dots. team = warp>>1, half = warp&1 ---
    {
        const int team = warp >> 1;          // 0..3
        const int half = warp & 1;           // 0/1
        const int koff = half * (KDIM / 2);  // element offset of this half

        // u-half into registers: 1024 elems / 32 lanes = 8 float4 per lane
        float4 ureg[8];
        const float4* uh = (const float4*)(uex + koff);
#pragma unroll
        for (int t = 0; t < 8; t++)
            ureg[t] = uh[lane + 32 * t];

        for (int c = team; c < cnt; c += 4) {
            const float4* vh = (const float4*)(g_V + (size_t)cidx[c] * KDIM + koff);

            float s[2] = {0.f, 0.f}, cp[2] = {0.f, 0.f};
#pragma unroll
            for (int t = 0; t < 8; t++) {
                float4 a = ureg[t];
                float4 b = __ldg(vh + lane + 32 * t);
                float p0 = __fmaf_rn(a.y, b.y, __fmul_rn(a.x, b.x));
                float p1 = __fmaf_rn(a.w, b.w, __fmul_rn(a.z, b.z));
                {
                    float y  = __fsub_rn(p0, cp[0]);
                    float s2 = __fadd_rn(s[0], y);
                    cp[0]    = __fsub_rn(__fsub_rn(s2, s[0]), y);
                    s[0]     = s2;
                }
                {
                    float y  = __fsub_rn(p1, cp[1]);
                    float s2 = __fadd_rn(s[1], y);
                    cp[1]    = __fsub_rn(__fsub_rn(s2, s[1]), y);
                    s[1]     = s2;
                }
            }
            // merge the 2 chains via TwoSum
            float S = s[0], CP = cp[0];
            {
                float t  = __fadd_rn(S, s[1]);
                float z  = __fsub_rn(t, S);
                float e  = __fadd_rn(__fsub_rn(S, __fsub_rn(t, z)), __fsub_rn(s[1], z));
                S  = t;
                CP = __fadd_rn(__fadd_rn(CP, cp[1]), e);
            }
            kahan_warp_reduce_pair(S, CP);
            if (lane == 0) { pS[c][half] = S; pCP[c][half] = CP; }
        }
    }
    __syncthreads();

    // merge halves deterministically (half0 + half1) per candidate
    if (tid < cnt) {
        float S0 = pS[tid][0], C0 = pCP[tid][0];
        float S1 = pS[tid][1], C1 = pCP[tid][1];
        float t  = __fadd_rn(S0, S1);
        float z  = __fsub_rn(t, S0);
        float e  = __fadd_rn(__fsub_rn(S0, __fsub_rn(t, z)), __fsub_rn(S1, z));
        cval[tid] = __fadd_rn(t, __fadd_rn(__fadd_rn(C0, C1), e));
    }
    __syncthreads();

    // exact top-k among candidates (tie: lowest index), scatter
    if (tid < cnt) {
        float my = cval[tid];
        int   mi = cidx[tid];
        int rank = 0;
        for (int j = 0; j < cnt; j++) {
            float vj = cval[j];
            if (vj > my || (vj == my && cidx[j] < mi)) rank++;
        }
        if (rank < k)
            rowp[mi] = my;
    }
}

// ---------------------------------------------------------------------------
extern "C" void kernel_launch(void* const* d_in, const int* in_sizes, int n_in,
                              void* d_out, int out_size) {
    const float* nodes  = (const float*)d_in[0];
    const float* pivots = (const float*)d_in[1];
    const float* W      = (const float*)d_in[2];
    const int*   topk   = (n_in > 3) ? (const int*)d_in[3] : nullptr;

    int N = in_sizes[0] / DIM;
    int M = in_sizes[1] / DIM;
    if (N > NMAX) N = NMAX;

    float* out = (float*)d_out;

    normalize_kernel<<<N, 256>>>(nodes,  W, N, 1.0f,   0);
    normalize_kernel<<<M, 256>>>(pivots, W, M, 0.125f, 1);

    dim3 ggrid(MPIV / 128, (N + 127) / 128);
    gemm_bf16_kernel<<<ggrid, 256>>>(N);

    select_refine_kernel<<<N, 256>>>(out, nodes, W, N, topk);

    (void)out_size;
}

// round 17
// speedup vs baseline: 1.0616x; 1.0232x over previous
#include <cuda_runtime.h>
#include <cuda_bf16.h>
#include <cstdint>

#define DIM   256
#define NPROJ 8
#define MPIV  2048
#define KDIM  2048
#define NMAX  50000
#define CANDCAP 64
#define LDSW  40       // smem row stride (bf16) -> conflict-free ldmatrix, 80B
#define STAGES 3

// Scratch (__device__ globals per allocation rules)
__device__ __nv_bfloat16 g_Ub[(size_t)NMAX * KDIM];   // bf16 nodes for phase-1 GEMM
__device__ __nv_bfloat16 g_Vb[(size_t)MPIV * KDIM];   // bf16 pivots
__device__ float         g_V [(size_t)MPIV * KDIM];   // exact fp32 pivots * 1/8 (L2-resident)
__device__ __nv_bfloat16 g_Cb[(size_t)NMAX * MPIV];   // approx attention, bf16

// ---------------------------------------------------------------------------
// Fused normalization (IEEE ops): one warp per (row, p); rows >= N are pivots.
// Nodes: bf16 only (rcp-mult — below bf16 ulp). Pivots: fp32 exact-div + bf16.
// ---------------------------------------------------------------------------
__global__ void normalize_kernel(const float* __restrict__ X,
                                 const float* __restrict__ P,
                                 const float* __restrict__ W,
                                 int N, int M) {
    int n = blockIdx.x;
    if (n >= N + M) return;
    const bool  isPivot = (n >= N);
    const int   row     = isPivot ? (n - N) : n;
    int p    = threadIdx.x >> 5;
    int lane = threadIdx.x & 31;

    const float* x = (isPivot ? P : X) + (size_t)row * DIM;
    const float* w = W + (size_t)p * DIM;

    float t[8];
    float s = 0.f;
#pragma unroll
    for (int j = 0; j < 8; j++) {
        int d = lane + 32 * j;
        float v = __fmul_rn(x[d], w[d]);
        t[j] = v;
        s = __fmaf_rn(v, v, s);
    }
#pragma unroll
    for (int off = 16; off; off >>= 1)
        s = __fadd_rn(s, __shfl_xor_sync(0xffffffffu, s, off));

    float nrm = fmaxf(__fsqrt_rn(s), 1e-12f);

    if (isPivot) {
        __nv_bfloat16* outb = g_Vb + (size_t)row * KDIM + p * DIM;
        float*         outf = g_V  + (size_t)row * KDIM + p * DIM;
#pragma unroll
        for (int j = 0; j < 8; j++) {
            float u = __fdiv_rn(t[j], nrm);                 // exact path for refine
            outb[lane + 32 * j] = __float2bfloat16(__fmul_rn(u, 0.125f));
            outf[lane + 32 * j] = __fmul_rn(u, 0.125f);     // 2^-3 exact
        }
    } else {
        float rinv = __frcp_rn(nrm);                        // bf16 output: 1ulp is nil
        __nv_bfloat16* outb = g_Ub + (size_t)row * KDIM + p * DIM;
#pragma unroll
        for (int j = 0; j < 8; j++)
            outb[lane + 32 * j] = __float2bfloat16(__fmul_rn(t[j], rinv));
    }
}

// ---------------------------------------------------------------------------
// Phase-1 bf16 tensor-core GEMM, 3-stage cp.async pipeline (proven; at the
// legacy-mma throughput ceiling).
// ---------------------------------------------------------------------------
__device__ __forceinline__ uint32_t smem_u32(const void* p) {
    return (uint32_t)__cvta_generic_to_shared(p);
}
__device__ __forceinline__ void cp_async16(void* dst, const void* src) {
    asm volatile("cp.async.cg.shared.global [%0], [%1], 16;\n"
                 :: "r"(smem_u32(dst)), "l"(src));
}
__device__ __forceinline__ void ldsm_x4(uint32_t* r, uint32_t addr) {
    asm volatile("ldmatrix.sync.aligned.m8n8.x4.shared.b16 {%0,%1,%2,%3}, [%4];"
                 : "=r"(r[0]), "=r"(r[1]), "=r"(r[2]), "=r"(r[3]) : "r"(addr));
}
__device__ __forceinline__ void mma_bf16(float* c, const uint32_t* a, const uint32_t* b) {
    asm volatile("mma.sync.aligned.m16n8k16.row.col.f32.bf16.bf16.f32 "
                 "{%0,%1,%2,%3}, {%4,%5,%6,%7}, {%8,%9}, {%0,%1,%2,%3};"
                 : "+f"(c[0]), "+f"(c[1]), "+f"(c[2]), "+f"(c[3])
                 : "r"(a[0]), "r"(a[1]), "r"(a[2]), "r"(a[3]), "r"(b[0]), "r"(b[1]));
}

__global__ void __launch_bounds__(256)
gemm_bf16_kernel(int nrows) {
    __shared__ __nv_bfloat16 As[STAGES][128 * LDSW];
    __shared__ __nv_bfloat16 Bs[STAGES][128 * LDSW];

    const int tid  = threadIdx.x;
    const int warp = tid >> 5, lane = tid & 31;
    const int wm = warp >> 1, wn = warp & 1;
    const int rowBase = blockIdx.y * 128;
    const int colBase = blockIdx.x * 128;
    const int NK = KDIM / 32;

    const __nv_bfloat16* A = g_Ub;
    const __nv_bfloat16* B = g_Vb;

    float acc[2][8][4];
#pragma unroll
    for (int mi = 0; mi < 2; mi++)
#pragma unroll
        for (int nj = 0; nj < 8; nj++)
#pragma unroll
            for (int q = 0; q < 4; q++) acc[mi][nj][q] = 0.f;

    auto issue = [&](int kt) {
        int s  = kt % STAGES;
        int k0 = kt * 32;
#pragma unroll
        for (int it = 0; it < 2; it++) {
            int idx = tid + it * 256;
            int r = idx >> 2, kc = idx & 3;
            int gr = rowBase + r; if (gr >= nrows) gr = nrows - 1;
            cp_async16(&As[s][r * LDSW + kc * 8], A + (size_t)gr * KDIM + k0 + kc * 8);
            cp_async16(&Bs[s][r * LDSW + kc * 8], B + (size_t)(colBase + r) * KDIM + k0 + kc * 8);
        }
        asm volatile("cp.async.commit_group;");
    };

    issue(0);
    issue(1);

    for (int kt = 0; kt < NK; kt++) {
        asm volatile("cp.async.wait_group 1;");
        __syncthreads();
        if (kt + 2 < NK) issue(kt + 2);
        else asm volatile("cp.async.commit_group;");

        const int s = kt % STAGES;
#pragma unroll
        for (int kk = 0; kk < 2; kk++) {
            const int ko = kk * 16;
            uint32_t a[2][4];
#pragma unroll
            for (int mi = 0; mi < 2; mi++) {
                int r = wm * 32 + mi * 16 + (lane & 15);
                int c = ko + (lane >> 4) * 8;
                ldsm_x4(a[mi], smem_u32(&As[s][r * LDSW + c]));
            }
            uint32_t b[8][2];
#pragma unroll
            for (int p = 0; p < 4; p++) {
                int r = wn * 64 + p * 16 + ((lane >> 4) & 1) * 8 + (lane & 7);
                int c = ko + ((lane >> 3) & 1) * 8;
                uint32_t rr[4];
                ldsm_x4(rr, smem_u32(&Bs[s][r * LDSW + c]));
                b[2 * p][0] = rr[0]; b[2 * p][1] = rr[1];
                b[2 * p + 1][0] = rr[2]; b[2 * p + 1][1] = rr[3];
            }
#pragma unroll
            for (int mi = 0; mi < 2; mi++)
#pragma unroll
                for (int nj = 0; nj < 8; nj++)
                    mma_bf16(acc[mi][nj], a[mi], b[nj]);
        }
    }

    const int g = lane >> 2, t = lane & 3;
#pragma unroll
    for (int mi = 0; mi < 2; mi++) {
        int r0 = rowBase + wm * 32 + mi * 16 + g;
#pragma unroll
        for (int nj = 0; nj < 8; nj++) {
            int col = colBase + wn * 64 + nj * 8 + 2 * t;
            if (r0 < nrows) {
                __nv_bfloat162 pv = __float22bfloat162_rn(
                    make_float2(acc[mi][nj][0], acc[mi][nj][1]));
                *(__nv_bfloat162*)(g_Cb + (size_t)r0 * MPIV + col) = pv;
            }
            if (r0 + 8 < nrows) {
                __nv_bfloat162 pv = __float22bfloat162_rn(
                    make_float2(acc[mi][nj][2], acc[mi][nj][3]));
                *(__nv_bfloat162*)(g_Cb + (size_t)(r0 + 8) * MPIV + col) = pv;
            }
        }
    }
}

// ---------------------------------------------------------------------------
// Fused select + refine (R15 proven structure).
//  - 16-bit monotone keys, 2-pass radix select of rank-(k+3)
//  - phase C: split-K=2. warp = (team of 4, half). u-half in 32 regs;
//    inner loop __ldg of v only (no LDS). Halves merged via TwoSum.
//  - u recompute via one __frcp_rn + muls (perturbation ~1e-10, 9x under budget)
// ---------------------------------------------------------------------------
__device__ __forceinline__ unsigned m16(unsigned u) {   // bf16 raw -> monotone 16-bit
    return (u & 0x8000u) ? ((~u) & 0xFFFFu) : (u | 0x8000u);
}

// warp reduction of a (S, CP) Kahan pair via TwoSum; valid on all lanes after
__device__ __forceinline__ void kahan_warp_reduce_pair(float& S, float& CP) {
#pragma unroll
    for (int off = 16; off; off >>= 1) {
        float s2 = __shfl_xor_sync(0xffffffffu, S, off);
        float c2 = __shfl_xor_sync(0xffffffffu, CP, off);
        float t  = __fadd_rn(S, s2);
        float z  = __fsub_rn(t, S);
        float e  = __fadd_rn(__fsub_rn(S, __fsub_rn(t, z)), __fsub_rn(s2, z));
        S  = t;
        CP = __fadd_rn(__fadd_rn(CP, c2), e);
    }
}

__global__ void __launch_bounds__(256, 4)
select_refine_kernel(float* __restrict__ out,
                     const float* __restrict__ nodes,
                     const float* __restrict__ W,
                     int nrows, const int* __restrict__ topk_ptr) {
    int row = blockIdx.x;
    if (row >= nrows) return;

    __shared__ float    uex[KDIM];
    __shared__ unsigned hist[256];
    __shared__ unsigned warpsum[8];
    __shared__ float    pS [CANDCAP][2];
    __shared__ float    pCP[CANDCAP][2];
    __shared__ float    cval[CANDCAP];
    __shared__ int      cidx[CANDCAP];
    __shared__ unsigned s_b0;
    __shared__ unsigned s_T;
    __shared__ int      s_krem;
    __shared__ int      s_cnt;

    float* rowp = out + (size_t)row * MPIV;
    const int tid  = threadIdx.x;
    const int warp = tid >> 5, lane = tid & 31;

    // 8 bf16 keys per thread in ONE uint4 load (non-coherent path)
    unsigned key[8];
    {
        uint4 kv = __ldg((const uint4*)(g_Cb + (size_t)row * MPIV + tid * 8));
        unsigned w0 = kv.x, w1 = kv.y, w2 = kv.z, w3 = kv.w;
        key[0] = m16(w0 & 0xFFFFu); key[1] = m16(w0 >> 16);
        key[2] = m16(w1 & 0xFFFFu); key[3] = m16(w1 >> 16);
        key[4] = m16(w2 & 0xFFFFu); key[5] = m16(w2 >> 16);
        key[6] = m16(w3 & 0xFFFFu); key[7] = m16(w3 >> 16);
    }

    int k = topk_ptr ? __ldg(topk_ptr) : 32;
    // zero the output row NOW -- stores drain behind all later phases
    {
        float4 z = make_float4(0.f, 0.f, 0.f, 0.f);
        for (int i = tid; i < MPIV / 4; i += 256) ((float4*)rowp)[i] = z;
    }
    if (k <= 0) return;
    if (k > CANDCAP - 3) k = CANDCAP - 3;   // dataset: k=32; guard the cap
    int R = k + 3;

    if (tid == 0) { s_krem = R; s_cnt = 0; }

    // exact-class u recompute (one reciprocal, elementwise multiply)
    {
        const float* x = nodes + (size_t)row * DIM;
        const float* w = W + (size_t)warp * DIM;
        float t[8];
        float s = 0.f;
#pragma unroll
        for (int j = 0; j < 8; j++) {
            int d = lane + 32 * j;
            float v = __fmul_rn(x[d], w[d]);
            t[j] = v;
            s = __fmaf_rn(v, v, s);
        }
#pragma unroll
        for (int off = 16; off; off >>= 1)
            s = __fadd_rn(s, __shfl_xor_sync(0xffffffffu, s, off));
        float nrm  = fmaxf(__fsqrt_rn(s), 1e-12f);
        float rinv = __frcp_rn(nrm);
#pragma unroll
        for (int j = 0; j < 8; j++)
            uex[warp * DIM + lane + 32 * j] = __fmul_rn(t[j], rinv);
    }
    __syncthreads();

    // --- 2-pass radix select (8-bit digits) of rank-R 16-bit key ---
#pragma unroll
    for (int pass = 0; pass < 2; pass++) {
        hist[tid] = 0u;
        __syncthreads();
        int krem = s_krem;
        unsigned b0 = (pass == 0) ? 0u : s_b0;
#pragma unroll
        for (int it = 0; it < 8; it++) {
            if (pass == 0)
                atomicAdd(&hist[key[it] >> 8], 1u);
            else if ((key[it] >> 8) == b0)
                atomicAdd(&hist[key[it] & 255u], 1u);
        }
        __syncthreads();
        unsigned h = hist[255 - tid];
        unsigned x = h;
#pragma unroll
        for (int off = 1; off < 32; off <<= 1) {
            unsigned y = __shfl_up_sync(0xffffffffu, x, off);
            if (lane >= off) x += y;
        }
        if (lane == 31) warpsum[warp] = x;
        __syncthreads();
        unsigned add = 0;
#pragma unroll
        for (int w = 0; w < 8; w++)
            add += (w < warp) ? warpsum[w] : 0u;
        unsigned S = x + add;
        if ((int)S >= krem && (int)(S - h) < krem) {
            if (pass == 0) s_b0 = (unsigned)(255 - tid);
            else           s_T  = (s_b0 << 8) | (unsigned)(255 - tid);
            s_krem = krem - (int)(S - h);
        }
        __syncthreads();
    }

    unsigned T = s_T;

    // gather candidates
#pragma unroll
    for (int it = 0; it < 8; it++) {
        if (key[it] >= T) {
            int slot = atomicAdd(&s_cnt, 1);
            if (slot < CANDCAP) cidx[slot] = tid * 8 + it;
        }
    }
    __syncthreads();
    int cnt = (s_cnt < CANDCAP) ? s_cnt : CANDCAP;

    // --- phase C: split-K=2 exact dots. team = warp>>1, half = warp&1 ---
    {
        const int team = warp >> 1;          // 0..3
        const int half = warp & 1;           // 0/1
        const int koff = half * (KDIM / 2);  // element offset of this half

        // u-half into registers: 1024 elems / 32 lanes = 8 float4 per lane
        float4 ureg[8];
        const float4* uh = (const float4*)(uex + koff);
#pragma unroll
        for (int t = 0; t < 8; t++)
            ureg[t] = uh[lane + 32 * t];

        for (int c = team; c < cnt; c += 4) {
            const float4* vh = (const float4*)(g_V + (size_t)cidx[c] * KDIM + koff);

            float s[2] = {0.f, 0.f}, cp[2] = {0.f, 0.f};
#pragma unroll
            for (int t = 0; t < 8; t++) {
                float4 a = ureg[t];
                float4 b = __ldg(vh + lane + 32 * t);
                float p0 = __fmaf_rn(a.y, b.y, __fmul_rn(a.x, b.x));
                float p1 = __fmaf_rn(a.w, b.w, __fmul_rn(a.z, b.z));
                {
                    float y  = __fsub_rn(p0, cp[0]);
                    float s2 = __fadd_rn(s[0], y);
                    cp[0]    = __fsub_rn(__fsub_rn(s2, s[0]), y);
                    s[0]     = s2;
                }
                {
                    float y  = __fsub_rn(p1, cp[1]);
                    float s2 = __fadd_rn(s[1], y);
                    cp[1]    = __fsub_rn(__fsub_rn(s2, s[1]), y);
                    s[1]     = s2;
                }
            }
            // merge the 2 chains via TwoSum
            float S = s[0], CP = cp[0];
            {
                float t  = __fadd_rn(S, s[1]);
                float z  = __fsub_rn(t, S);
                float e  = __fadd_rn(__fsub_rn(S, __fsub_rn(t, z)), __fsub_rn(s[1], z));
                S  = t;
                CP = __fadd_rn(__fadd_rn(CP, cp[1]), e);
            }
            kahan_warp_reduce_pair(S, CP);
            if (lane == 0) { pS[c][half] = S; pCP[c][half] = CP; }
        }
    }
    __syncthreads();

    // merge halves deterministically (half0 + half1) per candidate
    if (tid < cnt) {
        float S0 = pS[tid][0], C0 = pCP[tid][0];
        float S1 = pS[tid][1], C1 = pCP[tid][1];
        float t  = __fadd_rn(S0, S1);
        float z  = __fsub_rn(t, S0);
        float e  = __fadd_rn(__fsub_rn(S0, __fsub_rn(t, z)), __fsub_rn(S1, z));
        cval[tid] = __fadd_rn(t, __fadd_rn(__fadd_rn(C0, C1), e));
    }
    __syncthreads();

    // exact top-k among candidates (tie: lowest index), scatter
    if (tid < cnt) {
        float my = cval[tid];
        int   mi = cidx[tid];
        int rank = 0;
        for (int j = 0; j < cnt; j++) {
            float vj = cval[j];
            if (vj > my || (vj == my && cidx[j] < mi)) rank++;
        }
        if (rank < k)
            rowp[mi] = my;
    }
}

// ---------------------------------------------------------------------------
extern "C" void kernel_launch(void* const* d_in, const int* in_sizes, int n_in,
                              void* d_out, int out_size) {
    const float* nodes  = (const float*)d_in[0];
    const float* pivots = (const float*)d_in[1];
    const float* W      = (const float*)d_in[2];
    const int*   topk   = (n_in > 3) ? (const int*)d_in[3] : nullptr;

    int N = in_sizes[0] / DIM;
    int M = in_sizes[1] / DIM;
    if (N > NMAX) N = NMAX;

    float* out = (float*)d_out;

    normalize_kernel<<<N + M, 256>>>(nodes, pivots, W, N, M);

    dim3 ggrid(MPIV / 128, (N + 127) / 128);
    gemm_bf16_kernel<<<ggrid, 256>>>(N);

    select_refine_kernel<<<N, 256>>>(out, nodes, W, N, topk);

    (void)out_size;
}